// round 14
// baseline (speedup 1.0000x reference)
#include <cuda_runtime.h>
#include <cuda_fp16.h>
#include <math.h>

#define NV_MAX   1048576
#define MAX_SEG  50000
#define D        12
#define ROW_PAD  16          // halves per padded row = 32 bytes = 1 L2 sector
#define EPS      1e-12f
#define CHUNK    2048        // seg-id staging tile (8KB smem)
#define VPB      128         // voxels per block (2 lanes per voxel)

// Contiguous bounds: voxel v owns tokens [g_start[v], g_start[v+1]).
// Empty voxels are gap-filled (rare). g_start[n_voxels] = T.
__device__ int g_start[NV_MAX + 1];
// fp16 table repacked to 32B-aligned rows (one L2 sector per gather).
__device__ __align__(32) __half g_tab[MAX_SEG * ROW_PAD];

// Fused prep: blocks [0, bblocks) find run boundaries (4 tokens/thread;
// one predicated store per boundary, rare loop only for empty-voxel gaps);
// remaining blocks repack the table to fp16.
__global__ __launch_bounds__(256) void k_prep(const int*   __restrict__ vox,
                                              const float* __restrict__ table,
                                              int T, int n_voxels,
                                              int rows, int bblocks) {
    if (blockIdx.x < (unsigned)bblocks) {
        int i = blockIdx.x * 256 + threadIdx.x;
        int base = i * 4;
        if (base >= T) return;

        int4 q = __ldg((const int4*)vox + i);   // base is 4-aligned: OK
        int vals[5];
        vals[0] = q.x; vals[1] = q.y; vals[2] = q.z; vals[3] = q.w;
        vals[4] = (base + 4 >= T) ? -1 : __ldg(vox + base + 4);

        if (base == 0) {
            g_start[vals[0]] = 0;
            for (int w = 0; w < vals[0]; w++) g_start[w] = 0;            // rare
        }
#pragma unroll
        for (int j = 0; j < 4; j++) {
            int idx = base + j;
            int cur = vals[j];
            if (idx == T - 1) {
                g_start[n_voxels] = T;
                for (int w = cur + 1; w < n_voxels; w++) g_start[w] = T; // rare
            } else {
                int nx = vals[j + 1];
                if (nx != cur) {
                    g_start[nx] = idx + 1;                               // common
                    for (int w = cur + 1; w < nx; w++) g_start[w] = idx + 1; // rare
                }
            }
        }
    } else {
        int r = (blockIdx.x - bblocks) * 256 + threadIdx.x;
        if (r >= rows) return;
        const float4* src = (const float4*)(table + (size_t)r * D);
        float4 a = __ldg(src + 0);
        float4 b = __ldg(src + 1);
        float4 c = __ldg(src + 2);
        __half2 h[8];
        h[0] = __floats2half2_rn(a.x, a.y);
        h[1] = __floats2half2_rn(a.z, a.w);
        h[2] = __floats2half2_rn(b.x, b.y);
        h[3] = __floats2half2_rn(b.z, b.w);
        h[4] = __floats2half2_rn(c.x, c.y);
        h[5] = __floats2half2_rn(c.z, c.w);
        h[6] = __floats2half2_rn(0.f, 0.f);
        h[7] = __floats2half2_rn(0.f, 0.f);
        uint4* dst = (uint4*)(g_tab + (size_t)r * ROW_PAD);
        dst[0] = *(uint4*)&h[0];
        dst[1] = *(uint4*)&h[4];
    }
}

#define H2(u) (*(const __half2*)&(u))

__device__ __forceinline__ void acc_half4(float* acc, __half2 a, __half2 b,
                                          __half2 c, __half2 d) {
    float2 f;
    f = __half22float2(a); acc[0] += f.x; acc[1] += f.y;
    f = __half22float2(b); acc[2] += f.x; acc[3] += f.y;
    f = __half22float2(c); acc[4] += f.x; acc[5] += f.y;
    f = __half22float2(d); acc[6] += f.x; acc[7] += f.y;
}

// Pair-cooperative pool (R11 layout): lanes (2k,2k+1) share voxel k; even lane
// handles dims 0-7, odd lane dims 8-11(+pad). 1 L1 wavefront per token.
// Unroll-2 + fp16 pair pre-add; 32 regs -> 8 CTAs/SM (64 warps).
__global__ __launch_bounds__(256, 8) void k_pool(const int* __restrict__ seg,
                                                 float*     __restrict__ out,
                                                 int n_voxels) {
    __shared__ int s_seg[CHUNK];

    int tid = threadIdx.x;
    int p   = tid & 1;
    int v   = blockIdx.x * VPB + (tid >> 1);
    int v0  = blockIdx.x * VPB;
    int v1  = min(v0 + VPB, n_voxels);

    int rs = __ldg(&g_start[v0]);
    int re = __ldg(&g_start[v1]);

    int s, e;
    if (v < n_voxels) { s = __ldg(&g_start[v]); e = __ldg(&g_start[v + 1]); }
    else              { s = rs;                 e = rs;                     }

    float acc[8];
#pragma unroll
    for (int d = 0; d < 8; d++) acc[d] = 0.0f;

    for (int cbase = rs; cbase < re; cbase += CHUNK) {
        int clim = min(re, cbase + CHUNK);
        __syncthreads();
        for (int j = cbase + tid; j < clim; j += 256)
            s_seg[j - cbase] = __ldg(seg + j);
        __syncthreads();

        int t0 = max(s, cbase);
        int t1 = min(e, clim);
        int t  = t0;

        // unroll-2: 2 loads in flight, fp16 pre-add of the token pair
        for (; t + 1 < t1; t += 2) {
            int i0 = t - cbase;
            int sg0 = s_seg[i0];
            int sg1 = s_seg[i0 + 1];
            uint4 q0 = __ldg((const uint4*)(g_tab + (size_t)sg0 * ROW_PAD) + p);
            uint4 q1 = __ldg((const uint4*)(g_tab + (size_t)sg1 * ROW_PAD) + p);

            __half2 a0 = __hadd2(H2(q0.x), H2(q1.x));
            __half2 a1 = __hadd2(H2(q0.y), H2(q1.y));
            __half2 a2 = __hadd2(H2(q0.z), H2(q1.z));
            __half2 a3 = __hadd2(H2(q0.w), H2(q1.w));
            acc_half4(acc, a0, a1, a2, a3);
        }
        if (t < t1) {
            int sg = s_seg[t - cbase];
            uint4 q = __ldg((const uint4*)(g_tab + (size_t)sg * ROW_PAD) + p);
            acc_half4(acc, H2(q.x), H2(q.y), H2(q.z), H2(q.w));
        }
    }

    int cnt = e - s;
    float invc = 1.0f / (float)(cnt > 0 ? cnt : 1);

    float m[8];
    float n2p = 0.0f;
    int nd = p ? 4 : 8;
#pragma unroll
    for (int d = 0; d < 8; d++) {
        m[d] = acc[d] * invc;
        if (d < nd) n2p += m[d] * m[d];
    }
    float norm2 = n2p + __shfl_xor_sync(0xFFFFFFFFu, n2p, 1);
    float inv   = 1.0f / fmaxf(sqrtf(norm2), EPS);

    if (v < n_voxels) {
        float4* orow = (float4*)(out + (size_t)v * D);
        if (p == 0) {
            orow[0] = make_float4(m[0] * inv, m[1] * inv, m[2] * inv, m[3] * inv);
            orow[1] = make_float4(m[4] * inv, m[5] * inv, m[6] * inv, m[7] * inv);
        } else {
            orow[2] = make_float4(m[0] * inv, m[1] * inv, m[2] * inv, m[3] * inv);
        }
    }
}

extern "C" void kernel_launch(void* const* d_in, const int* in_sizes, int n_in,
                              void* d_out, int out_size) {
    const float* table = (const float*)d_in[0];
    const int*   seg   = (const int*)  d_in[1];
    const int*   vox   = (const int*)  d_in[2];
    float*       out   = (float*)      d_out;

    int rows     = in_sizes[0] / D;
    int T        = in_sizes[1];
    int n_voxels = out_size / D;

    int bblocks = (T / 4 + 255) / 256;
    int rblocks = (rows + 255) / 256;
    k_prep<<<bblocks + rblocks, 256>>>(vox, table, T, n_voxels, rows, bblocks);
    k_pool<<<(n_voxels + VPB - 1) / VPB, 256>>>(seg, out, n_voxels);
}

// round 15
// speedup vs baseline: 1.0634x; 1.0634x over previous
#include <cuda_runtime.h>
#include <cuda_fp16.h>
#include <math.h>

#define NV_MAX   1048576
#define MAX_SEG  50000
#define D        12
#define ROW_PAD  16          // halves per padded row = 32 bytes = 1 L2 sector
#define EPS      1e-12f
#define CHUNK    2048        // seg-id staging tile (8KB smem)
#define VPB      128         // voxels per block (2 lanes per voxel)

// Per-voxel token range (monotone via gap-fill for empty voxels).
__device__ int g_start[NV_MAX];
__device__ int g_end[NV_MAX];
// fp16 table repacked to 32B-aligned rows (one L2 sector per gather).
__device__ __align__(32) __half g_tab[MAX_SEG * ROW_PAD];

// Fused prep: blocks [0, bblocks) find run boundaries (8 tokens/thread via
// 2x int4, gap-fill keeps bounds monotone); remaining blocks repack table.
__global__ __launch_bounds__(256) void k_prep(const int*   __restrict__ vox,
                                              const float* __restrict__ table,
                                              int T, int n_voxels,
                                              int rows, int bblocks) {
    if (blockIdx.x < (unsigned)bblocks) {
        int i = blockIdx.x * 256 + threadIdx.x;
        int base = i * 8;
        if (base >= T) return;

        int4 qa = __ldg((const int4*)vox + i * 2);
        int4 qb = __ldg((const int4*)vox + i * 2 + 1);
        int vals[9];
        vals[0] = qa.x; vals[1] = qa.y; vals[2] = qa.z; vals[3] = qa.w;
        vals[4] = qb.x; vals[5] = qb.y; vals[6] = qb.z; vals[7] = qb.w;
        vals[8] = (base + 8 >= T) ? -1 : __ldg(vox + base + 8);

        if (base == 0) {
            for (int w = 0; w < vals[0]; w++) { g_start[w] = 0; g_end[w] = 0; }
            g_start[vals[0]] = 0;
        }
#pragma unroll
        for (int j = 0; j < 8; j++) {
            int idx = base + j;
            int cur = vals[j];
            if (idx == T - 1) {
                g_end[cur] = T;
                for (int w = cur + 1; w < n_voxels; w++) { g_start[w] = T; g_end[w] = T; }
            } else {
                int nx = vals[j + 1];
                if (nx != cur) {
                    g_end[cur]  = idx + 1;
                    g_start[nx] = idx + 1;
                    for (int w = cur + 1; w < nx; w++) { g_start[w] = idx + 1; g_end[w] = idx + 1; }
                }
            }
        }
    } else {
        int r = (blockIdx.x - bblocks) * 256 + threadIdx.x;
        if (r >= rows) return;
        const float4* src = (const float4*)(table + (size_t)r * D);
        float4 a = __ldg(src + 0);
        float4 b = __ldg(src + 1);
        float4 c = __ldg(src + 2);
        __half2 h[8];
        h[0] = __floats2half2_rn(a.x, a.y);
        h[1] = __floats2half2_rn(a.z, a.w);
        h[2] = __floats2half2_rn(b.x, b.y);
        h[3] = __floats2half2_rn(b.z, b.w);
        h[4] = __floats2half2_rn(c.x, c.y);
        h[5] = __floats2half2_rn(c.z, c.w);
        h[6] = __floats2half2_rn(0.f, 0.f);
        h[7] = __floats2half2_rn(0.f, 0.f);
        uint4* dst = (uint4*)(g_tab + (size_t)r * ROW_PAD);
        dst[0] = *(uint4*)&h[0];
        dst[1] = *(uint4*)&h[4];
    }
}

#define H2(u) (*(const __half2*)&(u))

__device__ __forceinline__ void acc_half4(float* acc, __half2 a, __half2 b,
                                          __half2 c, __half2 d) {
    float2 f;
    f = __half22float2(a); acc[0] += f.x; acc[1] += f.y;
    f = __half22float2(b); acc[2] += f.x; acc[3] += f.y;
    f = __half22float2(c); acc[4] += f.x; acc[5] += f.y;
    f = __half22float2(d); acc[6] += f.x; acc[7] += f.y;
}

// Pair-cooperative pool (R11, proven): lanes (2k,2k+1) share voxel k; even lane
// handles dims 0-7, odd lane dims 8-11(+pad). 1 L1 wavefront per token.
// Unroll-2 + fp16 pair pre-add; 32 regs -> 8 CTAs/SM (64 warps).
__global__ __launch_bounds__(256, 8) void k_pool(const int* __restrict__ seg,
                                                 float*     __restrict__ out,
                                                 int n_voxels) {
    __shared__ int s_seg[CHUNK];

    int tid = threadIdx.x;
    int p   = tid & 1;
    int v   = blockIdx.x * VPB + (tid >> 1);
    int v0  = blockIdx.x * VPB;
    int vL  = min(v0 + VPB - 1, n_voxels - 1);

    int rs = g_start[v0];
    int re = g_end[vL];

    int s, e;
    if (v < n_voxels) { s = g_start[v]; e = g_end[v]; }
    else              { s = rs;         e = rs;       }

    float acc[8];
#pragma unroll
    for (int d = 0; d < 8; d++) acc[d] = 0.0f;

    for (int cbase = rs; cbase < re; cbase += CHUNK) {
        int clim = min(re, cbase + CHUNK);
        __syncthreads();
        for (int j = cbase + tid; j < clim; j += 256)
            s_seg[j - cbase] = __ldg(seg + j);
        __syncthreads();

        int t0 = max(s, cbase);
        int t1 = min(e, clim);
        int t  = t0;

        // unroll-2: 2 loads in flight, fp16 pre-add of the token pair
        for (; t + 1 < t1; t += 2) {
            int i0 = t - cbase;
            int sg0 = s_seg[i0];
            int sg1 = s_seg[i0 + 1];
            uint4 q0 = __ldg((const uint4*)(g_tab + (size_t)sg0 * ROW_PAD) + p);
            uint4 q1 = __ldg((const uint4*)(g_tab + (size_t)sg1 * ROW_PAD) + p);

            __half2 a0 = __hadd2(H2(q0.x), H2(q1.x));
            __half2 a1 = __hadd2(H2(q0.y), H2(q1.y));
            __half2 a2 = __hadd2(H2(q0.z), H2(q1.z));
            __half2 a3 = __hadd2(H2(q0.w), H2(q1.w));
            acc_half4(acc, a0, a1, a2, a3);
        }
        if (t < t1) {
            int sg = s_seg[t - cbase];
            uint4 q = __ldg((const uint4*)(g_tab + (size_t)sg * ROW_PAD) + p);
            acc_half4(acc, H2(q.x), H2(q.y), H2(q.z), H2(q.w));
        }
    }

    int cnt = e - s;
    float invc = 1.0f / (float)(cnt > 0 ? cnt : 1);

    float m[8];
    float n2p = 0.0f;
    int nd = p ? 4 : 8;
#pragma unroll
    for (int d = 0; d < 8; d++) {
        m[d] = acc[d] * invc;
        if (d < nd) n2p += m[d] * m[d];
    }
    float norm2 = n2p + __shfl_xor_sync(0xFFFFFFFFu, n2p, 1);
    float inv   = 1.0f / fmaxf(sqrtf(norm2), EPS);

    if (v < n_voxels) {
        float4* orow = (float4*)(out + (size_t)v * D);
        if (p == 0) {
            orow[0] = make_float4(m[0] * inv, m[1] * inv, m[2] * inv, m[3] * inv);
            orow[1] = make_float4(m[4] * inv, m[5] * inv, m[6] * inv, m[7] * inv);
        } else {
            orow[2] = make_float4(m[0] * inv, m[1] * inv, m[2] * inv, m[3] * inv);
        }
    }
}

extern "C" void kernel_launch(void* const* d_in, const int* in_sizes, int n_in,
                              void* d_out, int out_size) {
    const float* table = (const float*)d_in[0];
    const int*   seg   = (const int*)  d_in[1];
    const int*   vox   = (const int*)  d_in[2];
    float*       out   = (float*)      d_out;

    int rows     = in_sizes[0] / D;
    int T        = in_sizes[1];
    int n_voxels = out_size / D;

    int bblocks = (T / 8 + 255) / 256;
    int rblocks = (rows + 255) / 256;
    k_prep<<<bblocks + rblocks, 256>>>(vox, table, T, n_voxels, rows, bblocks);
    k_pool<<<(n_voxels + VPB - 1) / VPB, 256>>>(seg, out, n_voxels);
}

// round 16
// speedup vs baseline: 1.0824x; 1.0178x over previous
#include <cuda_runtime.h>
#include <cuda_fp16.h>
#include <math.h>

#define NV_MAX   1048576
#define MAX_SEG  50000
#define D        12
#define ROW_PAD  16          // halves per padded row = 32 bytes = 1 L2 sector
#define EPS      1e-12f
#define CHUNK    2048        // seg-id staging tile (8KB smem)
#define VPB      128         // voxels per block (2 lanes per voxel)

// Per-voxel token range (monotone via gap-fill for empty voxels).
__device__ int g_start[NV_MAX];
__device__ int g_end[NV_MAX];
// fp16 table repacked to 32B-aligned rows (one L2 sector per gather).
__device__ __align__(32) __half g_tab[MAX_SEG * ROW_PAD];

// Fused prep: blocks [0, bblocks) find run boundaries (8 tokens/thread via
// 2x int4, gap-fill keeps bounds monotone); remaining blocks repack table.
__global__ __launch_bounds__(256) void k_prep(const int*   __restrict__ vox,
                                              const float* __restrict__ table,
                                              int T, int n_voxels,
                                              int rows, int bblocks) {
    if (blockIdx.x < (unsigned)bblocks) {
        int i = blockIdx.x * 256 + threadIdx.x;
        int base = i * 8;
        if (base >= T) return;

        int4 qa = __ldg((const int4*)vox + i * 2);
        int4 qb = __ldg((const int4*)vox + i * 2 + 1);
        int vals[9];
        vals[0] = qa.x; vals[1] = qa.y; vals[2] = qa.z; vals[3] = qa.w;
        vals[4] = qb.x; vals[5] = qb.y; vals[6] = qb.z; vals[7] = qb.w;
        vals[8] = (base + 8 >= T) ? -1 : __ldg(vox + base + 8);

        if (base == 0) {
            for (int w = 0; w < vals[0]; w++) { g_start[w] = 0; g_end[w] = 0; }
            g_start[vals[0]] = 0;
        }
#pragma unroll
        for (int j = 0; j < 8; j++) {
            int idx = base + j;
            int cur = vals[j];
            if (idx == T - 1) {
                g_end[cur] = T;
                for (int w = cur + 1; w < n_voxels; w++) { g_start[w] = T; g_end[w] = T; }
            } else {
                int nx = vals[j + 1];
                if (nx != cur) {
                    g_end[cur]  = idx + 1;
                    g_start[nx] = idx + 1;
                    for (int w = cur + 1; w < nx; w++) { g_start[w] = idx + 1; g_end[w] = idx + 1; }
                }
            }
        }
    } else {
        int r = (blockIdx.x - bblocks) * 256 + threadIdx.x;
        if (r >= rows) return;
        const float4* src = (const float4*)(table + (size_t)r * D);
        float4 a = __ldg(src + 0);
        float4 b = __ldg(src + 1);
        float4 c = __ldg(src + 2);
        __half2 h[8];
        h[0] = __floats2half2_rn(a.x, a.y);
        h[1] = __floats2half2_rn(a.z, a.w);
        h[2] = __floats2half2_rn(b.x, b.y);
        h[3] = __floats2half2_rn(b.z, b.w);
        h[4] = __floats2half2_rn(c.x, c.y);
        h[5] = __floats2half2_rn(c.z, c.w);
        h[6] = __floats2half2_rn(0.f, 0.f);
        h[7] = __floats2half2_rn(0.f, 0.f);
        uint4* dst = (uint4*)(g_tab + (size_t)r * ROW_PAD);
        dst[0] = *(uint4*)&h[0];
        dst[1] = *(uint4*)&h[4];
    }
}

#define H2(u) (*(const __half2*)&(u))

__device__ __forceinline__ void acc_half4(float* acc, __half2 a, __half2 b,
                                          __half2 c, __half2 d) {
    float2 f;
    f = __half22float2(a); acc[0] += f.x; acc[1] += f.y;
    f = __half22float2(b); acc[2] += f.x; acc[3] += f.y;
    f = __half22float2(c); acc[4] += f.x; acc[5] += f.y;
    f = __half22float2(d); acc[6] += f.x; acc[7] += f.y;
}

// Pair-cooperative pool: lanes (2k,2k+1) share voxel k; even lane handles
// dims 0-7, odd lane dims 8-11(+pad). 1 L1 wavefront per token gather.
// Unroll-2 + fp16 pair pre-add + LDS.64 seg fetch (parity-peeled).
// 32 regs -> 8 CTAs/SM (64 warps).
__global__ __launch_bounds__(256, 8) void k_pool(const int* __restrict__ seg,
                                                 float*     __restrict__ out,
                                                 int n_voxels) {
    __shared__ __align__(16) int s_seg[CHUNK];

    int tid = threadIdx.x;
    int p   = tid & 1;
    int v   = blockIdx.x * VPB + (tid >> 1);
    int v0  = blockIdx.x * VPB;
    int vL  = min(v0 + VPB - 1, n_voxels - 1);

    int rs = g_start[v0];
    int re = g_end[vL];

    int s, e;
    if (v < n_voxels) { s = g_start[v]; e = g_end[v]; }
    else              { s = rs;         e = rs;       }

    float acc[8];
#pragma unroll
    for (int d = 0; d < 8; d++) acc[d] = 0.0f;

    for (int cbase = rs; cbase < re; cbase += CHUNK) {
        int clim = min(re, cbase + CHUNK);
        __syncthreads();
        for (int j = cbase + tid; j < clim; j += 256)
            s_seg[j - cbase] = __ldg(seg + j);
        __syncthreads();

        int t0 = max(s, cbase);
        int t1 = min(e, clim);
        int t  = t0;

        // parity peel so (t - cbase) is even for the int2 fetch
        if (t < t1 && ((t - cbase) & 1)) {
            int sg = s_seg[t - cbase];
            uint4 q = __ldg((const uint4*)(g_tab + (size_t)sg * ROW_PAD) + p);
            acc_half4(acc, H2(q.x), H2(q.y), H2(q.z), H2(q.w));
            t++;
        }

        // unroll-2: one LDS.64 fetches both seg ids; 2 gathers in flight;
        // fp16 pre-add of the token pair
        for (; t + 1 < t1; t += 2) {
            int2 sgp = *(const int2*)(s_seg + (t - cbase));
            uint4 q0 = __ldg((const uint4*)(g_tab + (size_t)sgp.x * ROW_PAD) + p);
            uint4 q1 = __ldg((const uint4*)(g_tab + (size_t)sgp.y * ROW_PAD) + p);

            __half2 a0 = __hadd2(H2(q0.x), H2(q1.x));
            __half2 a1 = __hadd2(H2(q0.y), H2(q1.y));
            __half2 a2 = __hadd2(H2(q0.z), H2(q1.z));
            __half2 a3 = __hadd2(H2(q0.w), H2(q1.w));
            acc_half4(acc, a0, a1, a2, a3);
        }
        if (t < t1) {
            int sg = s_seg[t - cbase];
            uint4 q = __ldg((const uint4*)(g_tab + (size_t)sg * ROW_PAD) + p);
            acc_half4(acc, H2(q.x), H2(q.y), H2(q.z), H2(q.w));
        }
    }

    int cnt = e - s;
    float invc = 1.0f / (float)(cnt > 0 ? cnt : 1);

    float m[8];
    float n2p = 0.0f;
    int nd = p ? 4 : 8;
#pragma unroll
    for (int d = 0; d < 8; d++) {
        m[d] = acc[d] * invc;
        if (d < nd) n2p += m[d] * m[d];
    }
    float norm2 = n2p + __shfl_xor_sync(0xFFFFFFFFu, n2p, 1);
    float inv   = 1.0f / fmaxf(sqrtf(norm2), EPS);

    if (v < n_voxels) {
        float4* orow = (float4*)(out + (size_t)v * D);
        if (p == 0) {
            orow[0] = make_float4(m[0] * inv, m[1] * inv, m[2] * inv, m[3] * inv);
            orow[1] = make_float4(m[4] * inv, m[5] * inv, m[6] * inv, m[7] * inv);
        } else {
            orow[2] = make_float4(m[0] * inv, m[1] * inv, m[2] * inv, m[3] * inv);
        }
    }
}

extern "C" void kernel_launch(void* const* d_in, const int* in_sizes, int n_in,
                              void* d_out, int out_size) {
    const float* table = (const float*)d_in[0];
    const int*   seg   = (const int*)  d_in[1];
    const int*   vox   = (const int*)  d_in[2];
    float*       out   = (float*)      d_out;

    int rows     = in_sizes[0] / D;
    int T        = in_sizes[1];
    int n_voxels = out_size / D;

    int bblocks = (T / 8 + 255) / 256;
    int rblocks = (rows + 255) / 256;
    k_prep<<<bblocks + rblocks, 256>>>(vox, table, T, n_voxels, rows, bblocks);
    k_pool<<<(n_voxels + VPB - 1) / VPB, 256>>>(seg, out, n_voxels);
}